// round 11
// baseline (speedup 1.0000x reference)
#include <cuda_runtime.h>
#include <cstdint>

// SiLU(x) = x * sigmoid(x). HBM-bound streaming op.
// R11: final untested geometry cell — 4x 256-bit loads per thread, all
// front-batched (highest outstanding-bytes/SM of any variant: ~160KB), with
// streaming .cs both directions (best policy from the R2-R10 matrix).
// Block covers 32KB; grid 8192 for the 256MB case.

__device__ __forceinline__ float silu1(float x) {
    return x * (1.0f / (1.0f + __expf(-x)));
}

struct f8 { float v[8]; };

// 256-bit streaming load: 8 floats, evict-first.
__device__ __forceinline__ f8 ldg_cs_256(const void* p) {
    unsigned long long a, b, c, d;
    asm volatile("ld.global.cs.v4.b64 {%0,%1,%2,%3}, [%4];"
                 : "=l"(a), "=l"(b), "=l"(c), "=l"(d) : "l"(p));
    f8 r;
    r.v[0] = __uint_as_float((unsigned)a);  r.v[1] = __uint_as_float((unsigned)(a >> 32));
    r.v[2] = __uint_as_float((unsigned)b);  r.v[3] = __uint_as_float((unsigned)(b >> 32));
    r.v[4] = __uint_as_float((unsigned)c);  r.v[5] = __uint_as_float((unsigned)(c >> 32));
    r.v[6] = __uint_as_float((unsigned)d);  r.v[7] = __uint_as_float((unsigned)(d >> 32));
    return r;
}

// 256-bit streaming store: 8 floats.
__device__ __forceinline__ void stg_cs_256(void* p, const f8& r) {
    unsigned long long a = ((unsigned long long)__float_as_uint(r.v[1]) << 32) | __float_as_uint(r.v[0]);
    unsigned long long b = ((unsigned long long)__float_as_uint(r.v[3]) << 32) | __float_as_uint(r.v[2]);
    unsigned long long c = ((unsigned long long)__float_as_uint(r.v[5]) << 32) | __float_as_uint(r.v[4]);
    unsigned long long d = ((unsigned long long)__float_as_uint(r.v[7]) << 32) | __float_as_uint(r.v[6]);
    asm volatile("st.global.cs.v4.b64 [%0], {%1,%2,%3,%4};"
                 :: "l"(p), "l"(a), "l"(b), "l"(c), "l"(d) : "memory");
}

__device__ __forceinline__ f8 silu8(f8 x) {
    f8 r;
#pragma unroll
    for (int i = 0; i < 8; i++) r.v[i] = silu1(x.v[i]);
    return r;
}

#define TPB 256
#define LPT 4                          // 256-bit loads per thread
#define CHUNK_BYTES (TPB * 32 * LPT)   // 32KB per block
#define CHUNK_VECS (CHUNK_BYTES / 16)  // in float4 units (host math)

__global__ void __launch_bounds__(TPB) silu_v256x4(const float* __restrict__ in,
                                                   float* __restrict__ out) {
    const char* cin = (const char*)in + (size_t)blockIdx.x * CHUNK_BYTES;
    char* cout = (char*)out + (size_t)blockIdx.x * CHUNK_BYTES;
    unsigned off = threadIdx.x * 32u;

    f8 a[LPT];
#pragma unroll
    for (int k = 0; k < LPT; k++)
        a[k] = ldg_cs_256(cin + off + k * (TPB * 32u));   // 4 front-batched LDG.256

#pragma unroll
    for (int k = 0; k < LPT; k++)
        stg_cs_256(cout + off + k * (TPB * 32u), silu8(a[k]));
}

// Guarded fallback (float4 granularity) for shapes that don't divide evenly.
__global__ void __launch_bounds__(TPB) silu_guard(const float4* __restrict__ in,
                                                  float4* __restrict__ out,
                                                  int n_vec) {
    int base = blockIdx.x * (TPB * 4) + threadIdx.x;
#pragma unroll
    for (int k = 0; k < 4; k++) {
        int i = base + k * TPB;
        if (i < n_vec) {
            float4 v = __ldcs(&in[i]);
            float4 r;
            r.x = silu1(v.x); r.y = silu1(v.y); r.z = silu1(v.z); r.w = silu1(v.w);
            __stcs(&out[i], r);
        }
    }
}

// Scalar tail (n not divisible by 4; not hit for this shape)
__global__ void silu_tail(const float* __restrict__ in, float* __restrict__ out,
                          int start, int n) {
    int i = start + blockIdx.x * blockDim.x + threadIdx.x;
    if (i < n) {
        float x = in[i];
        out[i] = x * (1.0f / (1.0f + __expf(-x)));
    }
}

extern "C" void kernel_launch(void* const* d_in, const int* in_sizes, int n_in,
                              void* d_out, int out_size) {
    const float* x = (const float*)d_in[0];
    float* y = (float*)d_out;
    int n = in_sizes[0];

    int n_vec = n / 4;

    if (n_vec % CHUNK_VECS == 0) {
        int blocks = n_vec / CHUNK_VECS;     // 8192 for this shape
        silu_v256x4<<<blocks, TPB>>>(x, y);
    } else {
        int blocks = (n_vec + TPB * 4 - 1) / (TPB * 4);
        silu_guard<<<blocks, TPB>>>((const float4*)x, (float4*)y, n_vec);
    }

    int rem = n - n_vec * 4;
    if (rem > 0) {
        silu_tail<<<1, 256>>>(x, y, n_vec * 4, n);
    }
}

// round 12
// speedup vs baseline: 1.0171x; 1.0171x over previous
#include <cuda_runtime.h>
#include <cstdint>

// SiLU(x) = x * sigmoid(x). HBM-bound streaming op.
// FINAL (R9 lock-in): 256-bit global loads/stores (ld/st.global.cs.v4.b64),
// 2 per thread, front-batched; 16KB per 256-thread block; streaming (.cs)
// both directions. Measured across R2-R11, this is the Pareto-best variant:
// kernel ~74.0us, 6.50 TB/s (82.1% of spec) — the GB300 DRAM-controller floor
// for a 1:1 read/write stream (L2-residency and scheduling-policy alternatives
// all measured neutral or worse; carveout APIs are forbidden by the harness).

__device__ __forceinline__ float silu1(float x) {
    return x * (1.0f / (1.0f + __expf(-x)));
}

struct f8 { float v[8]; };

// 256-bit streaming load: 8 floats, evict-first.
__device__ __forceinline__ f8 ldg_cs_256(const void* p) {
    unsigned long long a, b, c, d;
    asm volatile("ld.global.cs.v4.b64 {%0,%1,%2,%3}, [%4];"
                 : "=l"(a), "=l"(b), "=l"(c), "=l"(d) : "l"(p));
    f8 r;
    r.v[0] = __uint_as_float((unsigned)a);  r.v[1] = __uint_as_float((unsigned)(a >> 32));
    r.v[2] = __uint_as_float((unsigned)b);  r.v[3] = __uint_as_float((unsigned)(b >> 32));
    r.v[4] = __uint_as_float((unsigned)c);  r.v[5] = __uint_as_float((unsigned)(c >> 32));
    r.v[6] = __uint_as_float((unsigned)d);  r.v[7] = __uint_as_float((unsigned)(d >> 32));
    return r;
}

// 256-bit streaming store: 8 floats.
__device__ __forceinline__ void stg_cs_256(void* p, const f8& r) {
    unsigned long long a = ((unsigned long long)__float_as_uint(r.v[1]) << 32) | __float_as_uint(r.v[0]);
    unsigned long long b = ((unsigned long long)__float_as_uint(r.v[3]) << 32) | __float_as_uint(r.v[2]);
    unsigned long long c = ((unsigned long long)__float_as_uint(r.v[5]) << 32) | __float_as_uint(r.v[4]);
    unsigned long long d = ((unsigned long long)__float_as_uint(r.v[7]) << 32) | __float_as_uint(r.v[6]);
    asm volatile("st.global.cs.v4.b64 [%0], {%1,%2,%3,%4};"
                 :: "l"(p), "l"(a), "l"(b), "l"(c), "l"(d) : "memory");
}

__device__ __forceinline__ f8 silu8(f8 x) {
    f8 r;
#pragma unroll
    for (int i = 0; i < 8; i++) r.v[i] = silu1(x.v[i]);
    return r;
}

#define TPB 256
#define CHUNK_BYTES 16384          // 16KB per block (two 8KB halves)
#define CHUNK_VECS 1024            // in float4 units (for host math)

// Exact-coverage: each thread does 2 x 32B loads at t*32 and 8192 + t*32.
__global__ void __launch_bounds__(TPB) silu_v256(const float* __restrict__ in,
                                                 float* __restrict__ out) {
    const char* cin = (const char*)in + (size_t)blockIdx.x * CHUNK_BYTES;
    char* cout = (char*)out + (size_t)blockIdx.x * CHUNK_BYTES;
    unsigned off0 = threadIdx.x * 32u;
    unsigned off1 = off0 + 8192u;

    f8 a = ldg_cs_256(cin + off0);
    f8 b = ldg_cs_256(cin + off1);

    stg_cs_256(cout + off0, silu8(a));
    stg_cs_256(cout + off1, silu8(b));
}

// Guarded fallback (float4 granularity) for shapes that don't divide evenly.
__global__ void __launch_bounds__(TPB) silu_guard(const float4* __restrict__ in,
                                                  float4* __restrict__ out,
                                                  int n_vec) {
    int base = blockIdx.x * (TPB * 4) + threadIdx.x;
#pragma unroll
    for (int k = 0; k < 4; k++) {
        int i = base + k * TPB;
        if (i < n_vec) {
            float4 v = __ldcs(&in[i]);
            float4 r;
            r.x = silu1(v.x); r.y = silu1(v.y); r.z = silu1(v.z); r.w = silu1(v.w);
            __stcs(&out[i], r);
        }
    }
}

// Scalar tail (n not divisible by 4; not hit for this shape)
__global__ void silu_tail(const float* __restrict__ in, float* __restrict__ out,
                          int start, int n) {
    int i = start + blockIdx.x * blockDim.x + threadIdx.x;
    if (i < n) {
        float x = in[i];
        out[i] = x * (1.0f / (1.0f + __expf(-x)));
    }
}

extern "C" void kernel_launch(void* const* d_in, const int* in_sizes, int n_in,
                              void* d_out, int out_size) {
    const float* x = (const float*)d_in[0];
    float* y = (float*)d_out;
    int n = in_sizes[0];

    int n_vec = n / 4;

    if (n_vec % CHUNK_VECS == 0) {
        int blocks = n_vec / CHUNK_VECS;     // 16384 for this shape
        silu_v256<<<blocks, TPB>>>(x, y);
    } else {
        int blocks = (n_vec + TPB * 4 - 1) / (TPB * 4);
        silu_guard<<<blocks, TPB>>>((const float4*)x, (float4*)y, n_vec);
    }

    int rem = n - n_vec * 4;
    if (rem > 0) {
        silu_tail<<<1, 256>>>(x, y, n_vec * 4, n);
    }
}